// round 17
// baseline (speedup 1.0000x reference)
#include <cuda_runtime.h>
#include <cuda_fp16.h>
#include <cstdint>
#include <stdint.h>
#include <math.h>

#define B_  32
#define D_  256
#define K_  1024
#define HW_ 1024
#define N_  32768
#define Q_ELEMS 8388608
#define ENC_OFF 8388610
#define CAND_T 6.0e-4f
#define CAND_MAX 16

// SMEM layout (bytes)
#define SM_AHI   0          // A fp16 [128][260] = 66560
#define SM_B     66560      // B 2 bufs x 8192
#define SM_CN    82944      // cnorm 4096
#define SM_SV    87040      // 256 floats (min reduce)
#define SM_RM    88064      // 128 floats rowmin
#define SM_CT    88576      // 128 int ctr
#define SM_LS    89088      // 128 x 16 int cand list = 8192
#define SMEM_TOTAL 97280

// -------- scratch --------
__device__ __half g_bimg[262144];     // [8 nc][16 ds][128 n][16 k] fp16 slabs
__device__ float g_cnorm[K_];
__device__ float g_znorm[N_];
__device__ int   g_idx[N_];
__device__ int   g_counts[K_];
__device__ float g_part[8192];

#define MMA16816(d, a, b) \
    asm volatile("mma.sync.aligned.m16n8k16.row.col.f32.f16.f16.f32 " \
        "{%0,%1,%2,%3}, {%4,%5,%6,%7}, {%8,%9}, {%0,%1,%2,%3};" \
        : "+f"((d)[0]), "+f"((d)[1]), "+f"((d)[2]), "+f"((d)[3]) \
        : "r"((a)[0]), "r"((a)[1]), "r"((a)[2]), "r"((a)[3]), \
          "r"((b)[0]), "r"((b)[1]))

static __device__ __forceinline__ uint32_t smem_u32(const void* p) {
    uint32_t a;
    asm("{ .reg .u64 t; cvta.to.shared.u64 t, %1; cvt.u32.u64 %0, t; }" : "=r"(a) : "l"(p));
    return a;
}
static __device__ __forceinline__ void cp_async16(uint32_t dst, const void* src) {
    asm volatile("cp.async.cg.shared.global [%0], [%1], 16;" :: "r"(dst), "l"(src) : "memory");
}
#define CP_COMMIT() asm volatile("cp.async.commit_group;" ::: "memory")
#define CP_WAIT1()  asm volatile("cp.async.wait_group 1;" ::: "memory")
#define CP_WAIT0()  asm volatile("cp.async.wait_group 0;" ::: "memory")

// -------- cnorm + zero counts --------
__global__ void cnorm_kernel(const float* __restrict__ cb) {
    int tid = threadIdx.x;
    int gtid = blockIdx.x * 256 + tid;
    if (gtid < K_) g_counts[gtid] = 0;
    int wid = tid >> 5, lane = tid & 31;
    int code = blockIdx.x * 8 + wid;
    float s = 0.f;
    #pragma unroll
    for (int j = 0; j < 8; j++) {
        float v = cb[(size_t)code * D_ + lane + 32 * j];
        s = fmaf(v, v, s);
    }
    #pragma unroll
    for (int o = 16; o > 0; o >>= 1) s += __shfl_down_sync(0xffffffffu, s, o);
    if (lane == 0) g_cnorm[code] = s;
}

// -------- znorm (identical arithmetic to the R2 kernel that matched reference) --------
__global__ void znorm_kernel(const float* __restrict__ z_e) {
    int r = blockIdx.x * 256 + threadIdx.x;
    int b = r >> 10, hw = r & 1023;
    const float* p = z_e + (size_t)b * (D_ * HW_) + hw;
    float s = 0.f;
    #pragma unroll 8
    for (int d = 0; d < D_; d++) {
        float v = p[(size_t)d * HW_];
        s = fmaf(v, v, s);
    }
    g_znorm[r] = s;
}

// -------- codebook -> fp16 packed slabs --------
__global__ void prep_b_kernel(const float* __restrict__ cb) {
    int e = blockIdx.x * 256 + threadIdx.x;   // 262144
    int code = e >> 8;
    int d = e & 255;
    float v = cb[(size_t)code * D_ + d];
    int nc = code >> 7, n = code & 127;
    int ds = d >> 4, k = d & 15;
    g_bimg[(size_t)(nc * 16 + ds) * 2048 + (size_t)n * 16 + k] = __float2half(v);
}

// -------- fused: HMMA GEMM + candidate filter + exact rescore + one-hot --------
__global__ void __launch_bounds__(256) vq_main_kernel(const float* __restrict__ z_e,
                                                      const float* __restrict__ cb,
                                                      float* __restrict__ out) {
    extern __shared__ char smem[];
    __half* Ah = (__half*)(smem + SM_AHI);     // [128][260]
    float*  cn = (float*)(smem + SM_CN);
    float*  sv = (float*)(smem + SM_SV);
    float*  rowmin = (float*)(smem + SM_RM);
    int*    ctr = (int*)(smem + SM_CT);
    int*    clist = (int*)(smem + SM_LS);
    uint32_t sbB = smem_u32(smem) + SM_B;

    int tid = threadIdx.x;
    int w = tid >> 5, lane = tid & 31;
    int g = lane >> 2, tg = lane & 3;
    int wM = w & 3, wN = w >> 2;               // 4 M-warps x 2 N-warps
    int R0 = blockIdx.x * 128;
    int b = R0 >> 10, hw0 = R0 & 1023;
    const float* zbase = z_e + (size_t)b * (D_ * HW_) + hw0;

    #pragma unroll
    for (int i = tid; i < K_; i += 256) cn[i] = g_cnorm[i];
    if (tid < 128) { rowmin[tid] = 3.402823466e38f; ctr[tid] = 0; }

    for (int e = tid; e < 32768; e += 256) {
        int d = e >> 7, r = e & 127;
        Ah[r * 260 + d] = __float2half(zbase[(size_t)d * HW_ + r]);
    }

    // issue cg0 B loads (8KB: 32B per thread)
    {
        const char* src = (const char*)g_bimg + (size_t)tid * 32;
        uint32_t dst = sbB + tid * 32;
        cp_async16(dst, src);
        cp_async16(dst + 16, src + 16);
        CP_COMMIT();
    }
    __syncthreads();

    float acc[2][8][4];
    #pragma unroll
    for (int mt = 0; mt < 2; mt++)
        #pragma unroll
        for (int nt = 0; nt < 8; nt++)
            #pragma unroll
            for (int c = 0; c < 4; c++) acc[mt][nt][c] = 0.f;

    for (int cg = 0; cg < 64; cg++) {           // 8KB per cg (2 ds-slabs)
        if (cg < 63) {
            const char* src = (const char*)g_bimg + (size_t)(cg + 1) * 8192 + (size_t)tid * 32;
            uint32_t dst = sbB + ((cg + 1) & 1) * 8192 + tid * 32;
            cp_async16(dst, src);
            cp_async16(dst + 16, src + 16);
            CP_COMMIT();
            CP_WAIT1();
        } else {
            CP_WAIT0();
        }
        __syncthreads();

        const __half* Bbuf = (const __half*)(smem + SM_B + (cg & 1) * 8192);
        int k0b = (cg & 7) * 32;                // d-offset within n0

        #pragma unroll
        for (int dsi = 0; dsi < 2; dsi++) {
            int k0 = k0b + dsi * 16;
            const __half* Bh = Bbuf + dsi * 2048;

            uint32_t ah[2][4], bh[8][2];
            #pragma unroll
            for (int mt = 0; mt < 2; mt++) {
                const __half* pa = Ah + (wM * 32 + mt * 16 + g) * 260 + k0 + tg * 2;
                ah[mt][0] = *(const uint32_t*)pa;
                ah[mt][1] = *(const uint32_t*)(pa + 8 * 260);
                ah[mt][2] = *(const uint32_t*)(pa + 8);
                ah[mt][3] = *(const uint32_t*)(pa + 8 * 260 + 8);
            }
            #pragma unroll
            for (int nt = 0; nt < 8; nt++) {
                const __half* pb = Bh + (wN * 64 + nt * 8 + g) * 16 + tg * 2;
                bh[nt][0] = *(const uint32_t*)pb;
                bh[nt][1] = *(const uint32_t*)(pb + 8);
            }
            #pragma unroll
            for (int mt = 0; mt < 2; mt++)
                #pragma unroll
                for (int nt = 0; nt < 8; nt++) MMA16816(acc[mt][nt], ah[mt], bh[nt]);
        }
        __syncthreads();

        if ((cg & 7) == 7) {
            int n0 = cg >> 3;
            // ---- Phase A: chunk row-min -> running rowmin ----
            float cmin[4];
            #pragma unroll
            for (int i = 0; i < 4; i++) cmin[i] = 3.402823466e38f;
            #pragma unroll
            for (int nt = 0; nt < 8; nt++)
                #pragma unroll
                for (int mt = 0; mt < 2; mt++)
                    #pragma unroll
                    for (int h = 0; h < 2; h++) {
                        int kc = n0 * 128 + wN * 64 + nt * 8 + tg * 2;
                        float d0 = cn[kc]     - 2.0f * acc[mt][nt][h * 2 + 0];
                        float d1 = cn[kc + 1] - 2.0f * acc[mt][nt][h * 2 + 1];
                        cmin[mt * 2 + h] = fminf(cmin[mt * 2 + h], fminf(d0, d1));
                    }
            #pragma unroll
            for (int i = 0; i < 4; i++) {
                float v = cmin[i];
                v = fminf(v, __shfl_xor_sync(0xffffffffu, v, 1));
                v = fminf(v, __shfl_xor_sync(0xffffffffu, v, 2));
                if (tg == 0) {
                    int mt = i >> 1, h = i & 1;
                    sv[wN * 128 + wM * 32 + mt * 16 + h * 8 + g] = v;
                }
            }
            __syncthreads();
            if (tid < 128)
                rowmin[tid] = fminf(rowmin[tid], fminf(sv[tid], sv[128 + tid]));
            __syncthreads();
            // ---- Phase B: filter & append candidates; reset acc ----
            #pragma unroll
            for (int nt = 0; nt < 8; nt++)
                #pragma unroll
                for (int mt = 0; mt < 2; mt++)
                    #pragma unroll
                    for (int h = 0; h < 2; h++) {
                        int kc = n0 * 128 + wN * 64 + nt * 8 + tg * 2;
                        int rowm = wM * 32 + mt * 16 + h * 8 + g;
                        float thr = rowmin[rowm] + CAND_T;
                        float d0 = cn[kc]     - 2.0f * acc[mt][nt][h * 2 + 0];
                        float d1 = cn[kc + 1] - 2.0f * acc[mt][nt][h * 2 + 1];
                        if (d0 <= thr) {
                            int p = atomicAdd(&ctr[rowm], 1);
                            if (p < CAND_MAX) clist[rowm * CAND_MAX + p] = kc;
                        }
                        if (d1 <= thr) {
                            int p = atomicAdd(&ctr[rowm], 1);
                            if (p < CAND_MAX) clist[rowm * CAND_MAX + p] = kc + 1;
                        }
                        acc[mt][nt][h * 2 + 0] = 0.f;
                        acc[mt][nt][h * 2 + 1] = 0.f;
                    }
            __syncthreads();
        }
    }

    // ---- tail: exact fp32 rescore of candidates (R2 arithmetic) + outputs ----
    float* zsT = (float*)(smem + SM_B);   // [8][256]
    for (int rb = 0; rb < 128; rb += 8) {
        __syncthreads();
        for (int i = tid; i < 2048; i += 256) {
            int d = i >> 3, r = i & 7;
            zsT[r * 256 + d] = zbase[(size_t)d * HW_ + rb + r];
        }
        __syncthreads();
        int row_l = rb + w;
        int rowg = R0 + row_l;
        int cnt = ctr[row_l];
        float zn = g_znorm[rowg];
        const float* zrow = zsT + w * 256;
        float bv = 3.402823466e38f;
        int bk = 0x7fffffff;
        if (cnt <= CAND_MAX) {
            for (int ci = lane; ci < cnt; ci += 32) {
                int k = clist[row_l * CAND_MAX + ci];
                const float* cp = cb + (size_t)k * D_;
                float dot = 0.f;
                #pragma unroll 8
                for (int d = 0; d < 256; d++) dot = fmaf(zrow[d], cp[d], dot);
                float A = zn + g_cnorm[k];
                float v = A - 2.0f * dot;
                if (v < bv || (v == bv && k < bk)) { bv = v; bk = k; }
            }
        } else {
            // overflow fallback: full exact scan (rare)
            #pragma unroll 1
            for (int j = 0; j < 32; j++) {
                int k = lane * 32 + j;
                const float* cp = cb + (size_t)k * D_;
                float dot = 0.f;
                #pragma unroll 8
                for (int d = 0; d < 256; d++) dot = fmaf(zrow[d], cp[d], dot);
                float A = zn + g_cnorm[k];
                float v = A - 2.0f * dot;
                if (v < bv || (v == bv && k < bk)) { bv = v; bk = k; }
            }
        }
        #pragma unroll
        for (int o = 16; o > 0; o >>= 1) {
            float ov = __shfl_xor_sync(0xffffffffu, bv, o);
            int   ok = __shfl_xor_sync(0xffffffffu, bk, o);
            if (ov < bv || (ov == bv && ok < bk)) { bv = ov; bk = ok; }
        }
        int kwin = __shfl_sync(0xffffffffu, bk, 0);
        if (lane == 0) {
            g_idx[rowg] = kwin;
            atomicAdd(&g_counts[kwin], 1);
        }
        // one-hot row write (coalesced float2)
        float2* rowp = (float2*)(out + ENC_OFF + (size_t)rowg * K_);
        int target = kwin >> 1;
        #pragma unroll
        for (int i = 0; i < 16; i++) {
            int p = i * 32 + lane;
            float2 v = make_float2(0.f, 0.f);
            if (p == target) { if (kwin & 1) v.y = 1.f; else v.x = 1.f; }
            rowp[p] = v;
        }
    }
}

// -------- gather quantized (NCHW) + per-block SSE partials --------
__global__ void output_kernel(const float* __restrict__ z_e,
                              const float* __restrict__ cb,
                              float* __restrict__ out) {
    __shared__ float red[8];
    int tid = threadIdx.x, wid = tid >> 5, lane = tid & 31;
    size_t e = ((size_t)blockIdx.x * 256 + tid) * 4;
    int w = (int)(e & 31);
    int h = (int)((e >> 5) & 31);
    int d = (int)((e >> 10) & 255);
    int b = (int)(e >> 18);
    int n = b * 1024 + h * 32 + w;
    float4 z = *reinterpret_cast<const float4*>(z_e + e);
    float q0 = cb[(size_t)g_idx[n + 0] * D_ + d];
    float q1 = cb[(size_t)g_idx[n + 1] * D_ + d];
    float q2 = cb[(size_t)g_idx[n + 2] * D_ + d];
    float q3 = cb[(size_t)g_idx[n + 3] * D_ + d];
    *reinterpret_cast<float4*>(out + e) = make_float4(q0, q1, q2, q3);
    float d0 = q0 - z.x, d1 = q1 - z.y, d2 = q2 - z.z, d3 = q3 - z.w;
    float v = d0 * d0 + d1 * d1 + d2 * d2 + d3 * d3;
    #pragma unroll
    for (int o = 16; o > 0; o >>= 1) v += __shfl_down_sync(0xffffffffu, v, o);
    if (lane == 0) red[wid] = v;
    __syncthreads();
    if (tid == 0) {
        float s = 0.f;
        #pragma unroll
        for (int i = 0; i < 8; i++) s += red[i];
        g_part[blockIdx.x] = s;
    }
}

// -------- finalize: loss + perplexity --------
__global__ void finalize_kernel(float* __restrict__ out) {
    __shared__ float red[1024];
    int t = threadIdx.x;
    float s = 0.f;
    #pragma unroll
    for (int i = 0; i < 8; i++) s += g_part[t + i * 1024];
    red[t] = s;
    __syncthreads();
    for (int o = 512; o > 0; o >>= 1) {
        if (t < o) red[t] += red[t + o];
        __syncthreads();
    }
    float sse = red[0];
    __syncthreads();
    float p = (float)g_counts[t] * (1.0f / 32768.0f);
    red[t] = p * logf(p + 1e-10f);
    __syncthreads();
    for (int o = 512; o > 0; o >>= 1) {
        if (t < o) red[t] += red[t + o];
        __syncthreads();
    }
    if (t == 0) {
        float mse = sse * (1.0f / 8388608.0f);
        out[Q_ELEMS]     = 1.25f * mse;
        out[Q_ELEMS + 1] = expf(-red[0]);
    }
}

extern "C" void kernel_launch(void* const* d_in, const int* in_sizes, int n_in,
                              void* d_out, int out_size) {
    const float* z_e = (const float*)d_in[0];
    const float* cb  = (const float*)d_in[1];
    if (n_in >= 2 && in_sizes[0] < in_sizes[1]) {
        z_e = (const float*)d_in[1];
        cb  = (const float*)d_in[0];
    }
    float* out = (float*)d_out;

    cudaFuncSetAttribute(vq_main_kernel, cudaFuncAttributeMaxDynamicSharedMemorySize, SMEM_TOTAL);

    cnorm_kernel<<<128, 256>>>(cb);
    znorm_kernel<<<128, 256>>>(z_e);
    prep_b_kernel<<<1024, 256>>>(cb);
    vq_main_kernel<<<256, 256, SMEM_TOTAL>>>(z_e, cb, out);
    output_kernel<<<8192, 256>>>(z_e, cb, out);
    finalize_kernel<<<1, 1024>>>(out);
}